// round 13
// baseline (speedup 1.0000x reference)
#include <cuda_runtime.h>
#include <cuda_fp16.h>
#include <math.h>
#include <stdint.h>

// Problem constants
#define BB 2
#define SS 4096
#define HH 2048
#define DD 2048
#define ND 6144   // 3*D

// ---------------------------------------------------------------------------
// Scratch (allocation-free: __device__ globals)
// ---------------------------------------------------------------------------
__device__ __half g_xh [(size_t)BB * SS * HH];    //  32 MB  LN output
__device__ __half g_qh [(size_t)BB * SS * ND];    //  96 MB  QKV output (Q,K,V)
__device__ float  g_sc [(size_t)BB * SS * SS];    // 128 MB  scores (fp32)
__device__ __half g_ph [(size_t)BB * SS * SS];    //  64 MB  probs (half)
__device__ __half g_ah [(size_t)BB * SS * DD];    //  32 MB  attn out
__device__ __half g_qTh[(size_t)ND * HH];         //  24 MB  qkv weight^T
__device__ __half g_oTh[(size_t)HH * DD];         //   8 MB  o_proj^T
__device__ __half g_vTh[(size_t)BB * DD * SS];    //  32 MB  V^T

// ---------------------------------------------------------------------------
// Helpers
// ---------------------------------------------------------------------------
__device__ __forceinline__ uint32_t smem_u32(const void* p) {
    uint32_t a;
    asm("{ .reg .u64 t; cvta.to.shared.u64 t, %1; cvt.u32.u64 %0, t; }" : "=r"(a) : "l"(p));
    return a;
}

__device__ __forceinline__ void cp_async16(uint32_t smem, const void* glob) {
    asm volatile("cp.async.cg.shared.global [%0], [%1], 16;" :: "r"(smem), "l"(glob));
}

__device__ __forceinline__ void ldmatrix_x4(uint32_t* r, uint32_t addr) {
    asm volatile("ldmatrix.sync.aligned.m8n8.x4.shared.b16 {%0,%1,%2,%3}, [%4];"
                 : "=r"(r[0]), "=r"(r[1]), "=r"(r[2]), "=r"(r[3]) : "r"(addr));
}

__device__ __forceinline__ void mma_f16(float* c, const uint32_t* a, const uint32_t* b) {
    asm volatile(
        "mma.sync.aligned.m16n8k16.row.col.f32.f16.f16.f32 "
        "{%0,%1,%2,%3}, {%4,%5,%6,%7}, {%8,%9}, {%0,%1,%2,%3};"
        : "+f"(c[0]), "+f"(c[1]), "+f"(c[2]), "+f"(c[3])
        : "r"(a[0]), "r"(a[1]), "r"(a[2]), "r"(a[3]), "r"(b[0]), "r"(b[1]));
}

// ---------------------------------------------------------------------------
// LayerNorm: fp32 in -> half out
// ---------------------------------------------------------------------------
__global__ void __launch_bounds__(256) ln_kernel(const float* __restrict__ x,
                                                 __half* __restrict__ xh)
{
    int row = blockIdx.x;
    const float4* xr = (const float4*)(x + (size_t)row * HH);
    __half2* yh = (__half2*)(xh + (size_t)row * HH);
    int tid = threadIdx.x;

    float4 v0 = xr[tid];
    float4 v1 = xr[tid + 256];
    float s  = v0.x + v0.y + v0.z + v0.w + v1.x + v1.y + v1.z + v1.w;
    float sq = v0.x*v0.x + v0.y*v0.y + v0.z*v0.z + v0.w*v0.w
             + v1.x*v1.x + v1.y*v1.y + v1.z*v1.z + v1.w*v1.w;

    __shared__ float rs[8], rq[8];
    #pragma unroll
    for (int o = 16; o > 0; o >>= 1) {
        s  += __shfl_xor_sync(0xffffffffu, s,  o);
        sq += __shfl_xor_sync(0xffffffffu, sq, o);
    }
    if ((tid & 31) == 0) { rs[tid >> 5] = s; rq[tid >> 5] = sq; }
    __syncthreads();
    float ts = 0.f, tq = 0.f;
    #pragma unroll
    for (int i = 0; i < 8; i++) { ts += rs[i]; tq += rq[i]; }

    float mean = ts * (1.0f / HH);
    float var  = tq * (1.0f / HH) - mean * mean;
    float rstd = rsqrtf(var + 1e-6f);

    yh[tid * 2 + 0]   = __floats2half2_rn((v0.x - mean) * rstd, (v0.y - mean) * rstd);
    yh[tid * 2 + 1]   = __floats2half2_rn((v0.z - mean) * rstd, (v0.w - mean) * rstd);
    yh[512 + tid * 2] = __floats2half2_rn((v1.x - mean) * rstd, (v1.y - mean) * rstd);
    yh[513 + tid * 2] = __floats2half2_rn((v1.z - mean) * rstd, (v1.w - mean) * rstd);
}

// ---------------------------------------------------------------------------
// Tiled transpose (TI in -> half out): out[c*ldo + r] = in[r*ldi + c]
// ---------------------------------------------------------------------------
template<typename TI>
__global__ void __launch_bounds__(256) transpose_kernel(
    const TI* __restrict__ in, __half* __restrict__ out,
    int ldi, int ldo, size_t sIz, size_t sOz)
{
    __shared__ float t[32][33];
    in  += (size_t)blockIdx.z * sIz;
    out += (size_t)blockIdx.z * sOz;
    int tx = threadIdx.x & 31, ty = threadIdx.x >> 5;   // 32 x 8
    int c = blockIdx.x * 32 + tx;
    int r = blockIdx.y * 32 + ty;
    #pragma unroll
    for (int j = 0; j < 4; j++) {
        float v;
        if (sizeof(TI) == 2) v = __half2float(((const __half*)in)[(size_t)(r + 8 * j) * ldi + c]);
        else                 v = ((const float*)in)[(size_t)(r + 8 * j) * ldi + c];
        t[ty + 8 * j][tx] = v;
    }
    __syncthreads();
    int co = blockIdx.y * 32 + tx;
    int ro = blockIdx.x * 32 + ty;
    #pragma unroll
    for (int j = 0; j < 4; j++)
        out[(size_t)(ro + 8 * j) * ldo + co] = __float2half_rn(t[tx][ty + 8 * j]);
}

// ---------------------------------------------------------------------------
// fp16 mma.sync NT GEMM: C[M,N] = A[M,K] @ B[N,K]^T (half, K-major).
// BM=128, BN=256, BK=64, 4-stage cp.async ring (prefetch distance 3),
// 8 warps of 64x64 warp tiles, 256 threads, one barrier per stage,
// DOUBLE-BUFFERED ldmatrix fragments (loads for slice ks+1 issued before
// the MMAs of slice ks, hiding ldmatrix latency under tensor work).
//   CAUSAL : skip output blocks entirely above the diagonal (scores)
//   KCAUS  : limit K loop to the diagonal (PV: A is lower-triangular)
// ---------------------------------------------------------------------------
#define BK 64
#define STAGE_BYTES 49152            // A 16KB + B 32KB
#define NSTAGE 4
#define GEMM_DYN_SMEM (NSTAGE * STAGE_BYTES)   // 196608

template<typename CT, bool CAUSAL, bool KCAUS, bool RES>
__global__ void __launch_bounds__(256, 1) hgemm(
    const __half* __restrict__ A, const __half* __restrict__ B,
    CT* __restrict__ C, const float* __restrict__ Resid,
    int K, int lda, int ldb, int ldc,
    size_t sAz, size_t sBz, size_t sCz)
{
    const int bx = blockIdx.x, by = blockIdx.y, bz = blockIdx.z;
    if (CAUSAL && bx * 256 > by * 128 + 127) return;

    extern __shared__ char sm[];
    const uint32_t s0 = smem_u32(sm);

    const int tid = threadIdx.x;
    const int wid = tid >> 5, lane = tid & 31;
    const int wm = (wid & 1) * 64;       // 2 warps along M
    const int wn = (wid >> 1) * 64;      // 4 warps along N

    const __half* Ab = A + (size_t)bz * sAz + (size_t)(by * 128) * lda;
    const __half* Bb = B + (size_t)bz * sBz + (size_t)(bx * 256) * ldb;

    // cp.async mapping: row = tid/2, chunks (tid&1)*4 .. +3 (pairs cover 8 chunks)
    const int ldRow = tid >> 1;
    const int ldCh0 = (tid & 1) * 4;

    float acc[4][8][4];
    #pragma unroll
    for (int i = 0; i < 4; i++)
        #pragma unroll
        for (int j = 0; j < 8; j++)
            #pragma unroll
            for (int h = 0; h < 4; h++) acc[i][j][h] = 0.f;

    int nk = K / BK;
    if (KCAUS) {
        int kmax = (by + 1) * 128;       // rows in this block see cols [0, kmax)
        if (kmax < K) nk = kmax / BK;
    }

    auto load_stage = [&](int kt, int st) {
        const int k0 = kt * BK;
        const uint32_t as = s0 + st * STAGE_BYTES;
        const uint32_t bs = as + 16384;
        const uint32_t rsw = (uint32_t)(ldRow & 7);
        #pragma unroll
        for (int i = 0; i < 4; i++) {
            const int ch = ldCh0 + i;
            const uint32_t off = (uint32_t)ldRow * 128 + (((uint32_t)ch ^ rsw) << 4);
            cp_async16(as + off, Ab + (size_t)ldRow * lda + k0 + ch * 8);
        }
        #pragma unroll
        for (int j = 0; j < 2; j++) {
            const int row = ldRow + j * 128;
            #pragma unroll
            for (int i = 0; i < 4; i++) {
                const int ch = ldCh0 + i;
                const uint32_t off = (uint32_t)row * 128 + (((uint32_t)ch ^ rsw) << 4);
                cp_async16(bs + off, Bb + (size_t)row * ldb + k0 + ch * 8);
            }
        }
        asm volatile("cp.async.commit_group;" ::: "memory");
    };

    // prologue: up to 3 stages in flight
    load_stage(0, 0);
    if (nk > 1) load_stage(1, 1);
    if (nk > 2) load_stage(2, 2);

    const uint32_t rlow = (uint32_t)(lane & 7);
    const uint32_t r16  = (uint32_t)(lane & 15);

    // double-buffered fragments
    uint32_t afr[2][4][4], bfr[2][8][2];

    auto load_frags = [&](uint32_t as, uint32_t bs, int ks, int buf) {
        const uint32_t ch = (uint32_t)(ks * 2 + (lane >> 4));
        const uint32_t sw = ((ch ^ rlow) << 4);
        #pragma unroll
        for (int mt = 0; mt < 4; mt++) {
            const uint32_t addr = as + (wm + mt * 16 + r16) * 128 + sw;
            ldmatrix_x4(afr[buf][mt], addr);
        }
        #pragma unroll
        for (int nb = 0; nb < 4; nb++) {
            uint32_t r[4];
            const uint32_t addr = bs + (wn + nb * 16 + r16) * 128 + sw;
            ldmatrix_x4(r, addr);
            bfr[buf][2 * nb + 0][0] = r[0]; bfr[buf][2 * nb + 0][1] = r[2];
            bfr[buf][2 * nb + 1][0] = r[1]; bfr[buf][2 * nb + 1][1] = r[3];
        }
    };

    int st = 0;
    for (int kt = 0; kt < nk; kt++) {
        // groups committed so far = min(kt+3, nk); need stages <= kt complete.
        if (kt + 3 <= nk) {
            asm volatile("cp.async.wait_group 2;" ::: "memory");
        } else if (kt + 2 <= nk) {
            asm volatile("cp.async.wait_group 1;" ::: "memory");
        } else {
            asm volatile("cp.async.wait_group 0;" ::: "memory");
        }
        // single barrier per stage: also guarantees every warp has finished
        // reading slot (kt+3)%NSTAGE (== (kt-1)%NSTAGE) before we overwrite it.
        __syncthreads();

        if (kt + 3 < nk) {
            int st2 = st + 3; if (st2 >= NSTAGE) st2 -= NSTAGE;
            load_stage(kt + 3, st2);
        }

        const uint32_t as = s0 + st * STAGE_BYTES;
        const uint32_t bs = as + 16384;

        load_frags(as, bs, 0, 0);
        #pragma unroll
        for (int ks = 0; ks < 4; ks++) {
            const int cur = ks & 1;
            if (ks < 3) load_frags(as, bs, ks + 1, cur ^ 1);
            #pragma unroll
            for (int mt = 0; mt < 4; mt++)
                #pragma unroll
                for (int nt = 0; nt < 8; nt++)
                    mma_f16(acc[mt][nt], afr[cur][mt], bfr[cur][nt]);
        }
        if (++st == NSTAGE) st = 0;
    }

    // epilogue
    const int qid = lane >> 2, tq = lane & 3;
    C += (size_t)bz * sCz;
    const int crow0 = by * 128 + wm;
    const int ccol0 = bx * 256 + wn;
    #pragma unroll
    for (int mt = 0; mt < 4; mt++) {
        #pragma unroll
        for (int h = 0; h < 2; h++) {
            const int row = crow0 + mt * 16 + qid + h * 8;
            CT* cr = C + (size_t)row * ldc;
            const float* rr = RES ? (Resid + (size_t)bz * sCz + (size_t)row * ldc) : nullptr;
            #pragma unroll
            for (int nt = 0; nt < 8; nt++) {
                const int col = ccol0 + nt * 8 + tq * 2;
                float vx = acc[mt][nt][2 * h + 0];
                float vy = acc[mt][nt][2 * h + 1];
                if (RES) {
                    const float2 rv = *(const float2*)(rr + col);
                    vx += rv.x; vy += rv.y;
                }
                if (sizeof(CT) == 2) {
                    *(__half2*)((__half*)cr + col) = __floats2half2_rn(vx, vy);
                } else {
                    *(float2*)((float*)cr + col) = make_float2(vx, vy);
                }
            }
        }
    }
}

// ---------------------------------------------------------------------------
// Causal softmax: fp32 scores in -> half probs out (zeros above diagonal)
// ---------------------------------------------------------------------------
__global__ void __launch_bounds__(256) softmax_kernel(
    const float* __restrict__ scores, __half* __restrict__ probs, float scale)
{
    const int r = blockIdx.x;
    const int b = blockIdx.y;
    const float* rin = scores + ((size_t)b * SS + r) * SS;
    __half* rout = probs + ((size_t)b * SS + r) * SS;
    const int len = r + 1;
    const int tid = threadIdx.x;

    __shared__ float buf[SS];
    __shared__ float red[8];

    float lmax = -1e30f;
    for (int t = tid; t < len; t += 256) {
        float v = rin[t] * scale;
        buf[t] = v;
        lmax = fmaxf(lmax, v);
    }
    #pragma unroll
    for (int o = 16; o > 0; o >>= 1)
        lmax = fmaxf(lmax, __shfl_xor_sync(0xffffffffu, lmax, o));
    if ((tid & 31) == 0) red[tid >> 5] = lmax;
    __syncthreads();
    float m = -1e30f;
    #pragma unroll
    for (int i = 0; i < 8; i++) m = fmaxf(m, red[i]);
    __syncthreads();

    float lsum = 0.f;
    for (int t = tid; t < len; t += 256) {
        float e = expf(buf[t] - m);
        buf[t] = e;
        lsum += e;
    }
    #pragma unroll
    for (int o = 16; o > 0; o >>= 1)
        lsum += __shfl_xor_sync(0xffffffffu, lsum, o);
    if ((tid & 31) == 0) red[tid >> 5] = lsum;
    __syncthreads();
    float tot = 0.f;
    #pragma unroll
    for (int i = 0; i < 8; i++) tot += red[i];
    const float inv = 1.0f / tot;

    for (int t = tid; t < len; t += 256) rout[t] = __float2half_rn(buf[t] * inv);
    const __half hz = __float2half_rn(0.f);
    for (int t = len + tid; t < SS; t += 256) rout[t] = hz;
}

// ---------------------------------------------------------------------------
// Launch
// ---------------------------------------------------------------------------
extern "C" void kernel_launch(void* const* d_in, const int* in_sizes, int n_in,
                              void* d_out, int out_size)
{
    (void)in_sizes; (void)n_in; (void)out_size;
    const float* x     = (const float*)d_in[0];   // (2, 4096, 2048)
    const float* qkvW  = (const float*)d_in[1];   // (2048, 6144)
    const float* oproj = (const float*)d_in[2];   // (2048, 2048)
    float* out = (float*)d_out;                   // (2, 4096, 2048)

    __half *xh, *qh, *ph, *ah, *qTh, *oTh, *vTh;
    float *sc;
    cudaGetSymbolAddress((void**)&xh,  g_xh);
    cudaGetSymbolAddress((void**)&qh,  g_qh);
    cudaGetSymbolAddress((void**)&sc,  g_sc);
    cudaGetSymbolAddress((void**)&ph,  g_ph);
    cudaGetSymbolAddress((void**)&ah,  g_ah);
    cudaGetSymbolAddress((void**)&qTh, g_qTh);
    cudaGetSymbolAddress((void**)&oTh, g_oTh);
    cudaGetSymbolAddress((void**)&vTh, g_vTh);

    cudaFuncSetAttribute(hgemm<__half, false, false, false>,
                         cudaFuncAttributeMaxDynamicSharedMemorySize, GEMM_DYN_SMEM);
    cudaFuncSetAttribute(hgemm<float, true, false, false>,
                         cudaFuncAttributeMaxDynamicSharedMemorySize, GEMM_DYN_SMEM);
    cudaFuncSetAttribute(hgemm<__half, false, true, false>,
                         cudaFuncAttributeMaxDynamicSharedMemorySize, GEMM_DYN_SMEM);
    cudaFuncSetAttribute(hgemm<float, false, false, true>,
                         cudaFuncAttributeMaxDynamicSharedMemorySize, GEMM_DYN_SMEM);

    const int M = BB * SS;                 // 8192
    const float scale = 1.0f / sqrtf((float)DD);

    // 1) LayerNorm -> half
    ln_kernel<<<M, 256>>>(x, xh);

    // 2) Weight transposes -> half
    transpose_kernel<float><<<dim3(ND / 32, HH / 32, 1), 256>>>(qkvW, qTh, ND, HH, 0, 0);
    transpose_kernel<float><<<dim3(HH / 32, DD / 32, 1), 256>>>(oproj, oTh, HH, DD, 0, 0);

    // 3) QKV GEMM: xh[8192,2048] @ qTh[6144,2048]^T -> qh[8192,6144]
    hgemm<__half, false, false, false><<<dim3(ND / 256, M / 128, 1), 256, GEMM_DYN_SMEM>>>(
        xh, qTh, qh, nullptr, HH, HH, HH, ND, 0, 0, 0);

    // 4) V transpose: V half [4096,2048] (ld=6144) -> vTh [2048,4096]
    transpose_kernel<__half><<<dim3(DD / 32, SS / 32, BB), 256>>>(
        qh + 2 * DD, vTh, ND, SS, (size_t)SS * ND, (size_t)DD * SS);

    // 5) Scores = Q @ K^T (causal block-skip) -> fp32
    hgemm<float, true, false, false><<<dim3(SS / 256, SS / 128, BB), 256, GEMM_DYN_SMEM>>>(
        qh, qh + DD, sc, nullptr, DD, ND, ND, SS,
        (size_t)SS * ND, (size_t)SS * ND, (size_t)SS * SS);

    // 6) Causal softmax: fp32 -> half probs
    softmax_kernel<<<dim3(SS, BB), 256>>>(sc, ph, scale);

    // 7) Attn = P @ V^T -> half (K-causal: skip zero columns of P)
    hgemm<__half, false, true, false><<<dim3(DD / 256, SS / 128, BB), 256, GEMM_DYN_SMEM>>>(
        ph, vTh, ah, nullptr, SS, SS, SS, DD,
        (size_t)SS * SS, (size_t)DD * SS, (size_t)SS * DD);

    // 8) Out = attn @ oTh^T + x  -> fp32
    hgemm<float, false, false, true><<<dim3(HH / 256, M / 128, 1), 256, GEMM_DYN_SMEM>>>(
        ah, oTh, out, x, DD, DD, DD, HH, 0, 0, 0);
}

// round 15
// speedup vs baseline: 1.0979x; 1.0979x over previous
#include <cuda_runtime.h>
#include <cuda_fp16.h>
#include <math.h>
#include <stdint.h>

// Problem constants
#define BB 2
#define SS 4096
#define HH 2048
#define DD 2048
#define ND 6144   // 3*D

// ---------------------------------------------------------------------------
// Scratch (allocation-free: __device__ globals)
// ---------------------------------------------------------------------------
__device__ __half g_xh [(size_t)BB * SS * HH];    //  32 MB  LN output
__device__ __half g_th [(size_t)BB * SS * DD];    //  32 MB  T = x @ (Wq Wk^T)
__device__ __half g_mt [(size_t)HH * HH];         //   8 MB  Mt[h',h] = sum_d Wk[h',d] Wq[h,d]
__device__ float  g_sc [(size_t)BB * SS * SS];    // 128 MB  scores (fp32)
__device__ __half g_ph [(size_t)BB * SS * SS];    //  64 MB  probs (half)
__device__ __half g_ah [(size_t)BB * SS * DD];    //  32 MB  attn out
__device__ __half g_wh [(size_t)HH * ND];         //  24 MB  qkvW cast to half (same layout)
__device__ __half g_qTh[(size_t)ND * HH];         //  24 MB  qkv weight^T (rows: Wq^T, Wk^T, Wv^T)
__device__ __half g_oTh[(size_t)HH * DD];         //   8 MB  o_proj^T
__device__ __half g_vTt[(size_t)DD * (BB * SS)];  //  32 MB  V^T  [2048, 8192]

// ---------------------------------------------------------------------------
// Helpers
// ---------------------------------------------------------------------------
__device__ __forceinline__ uint32_t smem_u32(const void* p) {
    uint32_t a;
    asm("{ .reg .u64 t; cvta.to.shared.u64 t, %1; cvt.u32.u64 %0, t; }" : "=r"(a) : "l"(p));
    return a;
}

__device__ __forceinline__ void cp_async16(uint32_t smem, const void* glob) {
    asm volatile("cp.async.cg.shared.global [%0], [%1], 16;" :: "r"(smem), "l"(glob));
}

__device__ __forceinline__ void ldmatrix_x4(uint32_t* r, uint32_t addr) {
    asm volatile("ldmatrix.sync.aligned.m8n8.x4.shared.b16 {%0,%1,%2,%3}, [%4];"
                 : "=r"(r[0]), "=r"(r[1]), "=r"(r[2]), "=r"(r[3]) : "r"(addr));
}

__device__ __forceinline__ void mma_f16(float* c, const uint32_t* a, const uint32_t* b) {
    asm volatile(
        "mma.sync.aligned.m16n8k16.row.col.f32.f16.f16.f32 "
        "{%0,%1,%2,%3}, {%4,%5,%6,%7}, {%8,%9}, {%0,%1,%2,%3};"
        : "+f"(c[0]), "+f"(c[1]), "+f"(c[2]), "+f"(c[3])
        : "r"(a[0]), "r"(a[1]), "r"(a[2]), "r"(a[3]), "r"(b[0]), "r"(b[1]));
}

// ---------------------------------------------------------------------------
// fp32 -> fp16 cast (same layout), vectorized
// ---------------------------------------------------------------------------
__global__ void __launch_bounds__(256) cast_kernel(const float* __restrict__ in,
                                                   __half* __restrict__ out, size_t n4)
{
    size_t i = (size_t)blockIdx.x * 256 + threadIdx.x;
    if (i < n4) {
        float4 v = ((const float4*)in)[i];
        __half2* o = (__half2*)out + i * 2;
        o[0] = __floats2half2_rn(v.x, v.y);
        o[1] = __floats2half2_rn(v.z, v.w);
    }
}

// ---------------------------------------------------------------------------
// LayerNorm: fp32 in -> half out
// ---------------------------------------------------------------------------
__global__ void __launch_bounds__(256) ln_kernel(const float* __restrict__ x,
                                                 __half* __restrict__ xh)
{
    int row = blockIdx.x;
    const float4* xr = (const float4*)(x + (size_t)row * HH);
    __half2* yh = (__half2*)(xh + (size_t)row * HH);
    int tid = threadIdx.x;

    float4 v0 = xr[tid];
    float4 v1 = xr[tid + 256];
    float s  = v0.x + v0.y + v0.z + v0.w + v1.x + v1.y + v1.z + v1.w;
    float sq = v0.x*v0.x + v0.y*v0.y + v0.z*v0.z + v0.w*v0.w
             + v1.x*v1.x + v1.y*v1.y + v1.z*v1.z + v1.w*v1.w;

    __shared__ float rs[8], rq[8];
    #pragma unroll
    for (int o = 16; o > 0; o >>= 1) {
        s  += __shfl_xor_sync(0xffffffffu, s,  o);
        sq += __shfl_xor_sync(0xffffffffu, sq, o);
    }
    if ((tid & 31) == 0) { rs[tid >> 5] = s; rq[tid >> 5] = sq; }
    __syncthreads();
    float ts = 0.f, tq = 0.f;
    #pragma unroll
    for (int i = 0; i < 8; i++) { ts += rs[i]; tq += rq[i]; }

    float mean = ts * (1.0f / HH);
    float var  = tq * (1.0f / HH) - mean * mean;
    float rstd = rsqrtf(var + 1e-6f);

    yh[tid * 2 + 0]   = __floats2half2_rn((v0.x - mean) * rstd, (v0.y - mean) * rstd);
    yh[tid * 2 + 1]   = __floats2half2_rn((v0.z - mean) * rstd, (v0.w - mean) * rstd);
    yh[512 + tid * 2] = __floats2half2_rn((v1.x - mean) * rstd, (v1.y - mean) * rstd);
    yh[513 + tid * 2] = __floats2half2_rn((v1.z - mean) * rstd, (v1.w - mean) * rstd);
}

// ---------------------------------------------------------------------------
// Tiled transpose (fp32 in -> half out): out[c*ldo + r] = in[r*ldi + c]
// ---------------------------------------------------------------------------
__global__ void __launch_bounds__(256) transpose_kernel(
    const float* __restrict__ in, __half* __restrict__ out,
    int ldi, int ldo)
{
    __shared__ float t[32][33];
    int tx = threadIdx.x & 31, ty = threadIdx.x >> 5;   // 32 x 8
    int c = blockIdx.x * 32 + tx;
    int r = blockIdx.y * 32 + ty;
    #pragma unroll
    for (int j = 0; j < 4; j++)
        t[ty + 8 * j][tx] = in[(size_t)(r + 8 * j) * ldi + c];
    __syncthreads();
    int co = blockIdx.y * 32 + tx;
    int ro = blockIdx.x * 32 + ty;
    #pragma unroll
    for (int j = 0; j < 4; j++)
        out[(size_t)(ro + 8 * j) * ldo + co] = __float2half_rn(t[tx][ty + 8 * j]);
}

// ---------------------------------------------------------------------------
// fp16 mma.sync NT GEMM: C[M,N] = A[M,K] @ B[N,K]^T (half, K-major).
// BM=128, BN=256, BK=64, 4-stage cp.async ring (prefetch distance 3),
// 8 warps of 64x64 warp tiles, 256 threads, one barrier per stage.
//   CAUSAL : skip output blocks entirely above the diagonal (scores)
//   KCAUS  : limit K loop to the diagonal (PV: A is lower-triangular)
// ---------------------------------------------------------------------------
#define BK 64
#define STAGE_BYTES 49152            // A 16KB + B 32KB
#define NSTAGE 4
#define GEMM_DYN_SMEM (NSTAGE * STAGE_BYTES)   // 196608

template<typename CT, bool CAUSAL, bool KCAUS, bool RES>
__global__ void __launch_bounds__(256, 1) hgemm(
    const __half* __restrict__ A, const __half* __restrict__ B,
    CT* __restrict__ C, const float* __restrict__ Resid,
    int K, int lda, int ldb, int ldc,
    size_t sAz, size_t sBz, size_t sCz)
{
    const int bx = blockIdx.x, by = blockIdx.y, bz = blockIdx.z;
    if (CAUSAL && bx * 256 > by * 128 + 127) return;

    extern __shared__ char sm[];
    const uint32_t s0 = smem_u32(sm);

    const int tid = threadIdx.x;
    const int wid = tid >> 5, lane = tid & 31;
    const int wm = (wid & 1) * 64;       // 2 warps along M
    const int wn = (wid >> 1) * 64;      // 4 warps along N

    const __half* Ab = A + (size_t)bz * sAz + (size_t)(by * 128) * lda;
    const __half* Bb = B + (size_t)bz * sBz + (size_t)(bx * 256) * ldb;

    // cp.async mapping: row = tid/2, chunks (tid&1)*4 .. +3 (pairs cover 8 chunks)
    const int ldRow = tid >> 1;
    const int ldCh0 = (tid & 1) * 4;

    float acc[4][8][4];
    #pragma unroll
    for (int i = 0; i < 4; i++)
        #pragma unroll
        for (int j = 0; j < 8; j++)
            #pragma unroll
            for (int h = 0; h < 4; h++) acc[i][j][h] = 0.f;

    int nk = K / BK;
    if (KCAUS) {
        int kmax = (by + 1) * 128;       // rows in this block see cols [0, kmax)
        if (kmax < K) nk = kmax / BK;
    }

    auto load_stage = [&](int kt, int st) {
        const int k0 = kt * BK;
        const uint32_t as = s0 + st * STAGE_BYTES;
        const uint32_t bs = as + 16384;
        const uint32_t rsw = (uint32_t)(ldRow & 7);
        #pragma unroll
        for (int i = 0; i < 4; i++) {
            const int ch = ldCh0 + i;
            const uint32_t off = (uint32_t)ldRow * 128 + (((uint32_t)ch ^ rsw) << 4);
            cp_async16(as + off, Ab + (size_t)ldRow * lda + k0 + ch * 8);
        }
        #pragma unroll
        for (int j = 0; j < 2; j++) {
            const int row = ldRow + j * 128;
            #pragma unroll
            for (int i = 0; i < 4; i++) {
                const int ch = ldCh0 + i;
                const uint32_t off = (uint32_t)row * 128 + (((uint32_t)ch ^ rsw) << 4);
                cp_async16(bs + off, Bb + (size_t)row * ldb + k0 + ch * 8);
            }
        }
        asm volatile("cp.async.commit_group;" ::: "memory");
    };

    // prologue: up to 3 stages in flight
    load_stage(0, 0);
    if (nk > 1) load_stage(1, 1);
    if (nk > 2) load_stage(2, 2);

    const uint32_t rlow = (uint32_t)(lane & 7);
    const uint32_t r16  = (uint32_t)(lane & 15);

    int st = 0;
    for (int kt = 0; kt < nk; kt++) {
        if (kt + 3 <= nk) {
            asm volatile("cp.async.wait_group 2;" ::: "memory");
        } else if (kt + 2 <= nk) {
            asm volatile("cp.async.wait_group 1;" ::: "memory");
        } else {
            asm volatile("cp.async.wait_group 0;" ::: "memory");
        }
        __syncthreads();

        if (kt + 3 < nk) {
            int st2 = st + 3; if (st2 >= NSTAGE) st2 -= NSTAGE;
            load_stage(kt + 3, st2);
        }

        const uint32_t as = s0 + st * STAGE_BYTES;
        const uint32_t bs = as + 16384;

        #pragma unroll
        for (int ks = 0; ks < 4; ks++) {
            const uint32_t ch = (uint32_t)(ks * 2 + (lane >> 4));
            const uint32_t sw = ((ch ^ rlow) << 4);
            uint32_t a[4][4], b[8][2];
            #pragma unroll
            for (int mt = 0; mt < 4; mt++) {
                const uint32_t addr = as + (wm + mt * 16 + r16) * 128 + sw;
                ldmatrix_x4(a[mt], addr);
            }
            #pragma unroll
            for (int nb = 0; nb < 4; nb++) {
                uint32_t r[4];
                const uint32_t addr = bs + (wn + nb * 16 + r16) * 128 + sw;
                ldmatrix_x4(r, addr);
                b[2 * nb + 0][0] = r[0]; b[2 * nb + 0][1] = r[2];
                b[2 * nb + 1][0] = r[1]; b[2 * nb + 1][1] = r[3];
            }
            #pragma unroll
            for (int mt = 0; mt < 4; mt++)
                #pragma unroll
                for (int nt = 0; nt < 8; nt++)
                    mma_f16(acc[mt][nt], a[mt], b[nt]);
        }
        if (++st == NSTAGE) st = 0;
    }

    // epilogue
    const int qid = lane >> 2, tq = lane & 3;
    C += (size_t)bz * sCz;
    const int crow0 = by * 128 + wm;
    const int ccol0 = bx * 256 + wn;
    #pragma unroll
    for (int mt = 0; mt < 4; mt++) {
        #pragma unroll
        for (int h = 0; h < 2; h++) {
            const int row = crow0 + mt * 16 + qid + h * 8;
            CT* cr = C + (size_t)row * ldc;
            const float* rr = RES ? (Resid + (size_t)bz * sCz + (size_t)row * ldc) : nullptr;
            #pragma unroll
            for (int nt = 0; nt < 8; nt++) {
                const int col = ccol0 + nt * 8 + tq * 2;
                float vx = acc[mt][nt][2 * h + 0];
                float vy = acc[mt][nt][2 * h + 1];
                if (RES) {
                    const float2 rv = *(const float2*)(rr + col);
                    vx += rv.x; vy += rv.y;
                }
                if (sizeof(CT) == 2) {
                    *(__half2*)((__half*)cr + col) = __floats2half2_rn(vx, vy);
                } else {
                    *(float2*)((float*)cr + col) = make_float2(vx, vy);
                }
            }
        }
    }
}

// ---------------------------------------------------------------------------
// Causal softmax: fp32 scores in -> half probs out (zeros above diagonal)
// ---------------------------------------------------------------------------
__global__ void __launch_bounds__(256) softmax_kernel(
    const float* __restrict__ scores, __half* __restrict__ probs, float scale)
{
    const int r = blockIdx.x;
    const int b = blockIdx.y;
    const float* rin = scores + ((size_t)b * SS + r) * SS;
    __half* rout = probs + ((size_t)b * SS + r) * SS;
    const int len = r + 1;
    const int tid = threadIdx.x;

    __shared__ float buf[SS];
    __shared__ float red[8];

    float lmax = -1e30f;
    for (int t = tid; t < len; t += 256) {
        float v = rin[t] * scale;
        buf[t] = v;
        lmax = fmaxf(lmax, v);
    }
    #pragma unroll
    for (int o = 16; o > 0; o >>= 1)
        lmax = fmaxf(lmax, __shfl_xor_sync(0xffffffffu, lmax, o));
    if ((tid & 31) == 0) red[tid >> 5] = lmax;
    __syncthreads();
    float m = -1e30f;
    #pragma unroll
    for (int i = 0; i < 8; i++) m = fmaxf(m, red[i]);
    __syncthreads();

    float lsum = 0.f;
    for (int t = tid; t < len; t += 256) {
        float e = expf(buf[t] - m);
        buf[t] = e;
        lsum += e;
    }
    #pragma unroll
    for (int o = 16; o > 0; o >>= 1)
        lsum += __shfl_xor_sync(0xffffffffu, lsum, o);
    if ((tid & 31) == 0) red[tid >> 5] = lsum;
    __syncthreads();
    float tot = 0.f;
    #pragma unroll
    for (int i = 0; i < 8; i++) tot += red[i];
    const float inv = 1.0f / tot;

    for (int t = tid; t < len; t += 256) rout[t] = __float2half_rn(buf[t] * inv);
    const __half hz = __float2half_rn(0.f);
    for (int t = len + tid; t < SS; t += 256) rout[t] = hz;
}

// ---------------------------------------------------------------------------
// Launch
//
// scores = Q K^T = x (Wq Wk^T) x^T. Precompute Mt[h',h] = sum_d Wk[h',d] Wq[h,d]
// (contraction over the OUTPUT dim d — operands must be d-contiguous, i.e. the
// original qkvW layout cast to half). Then T = xh @ Mt^T, scores = T @ xh^T.
// Replaces the Q,K GEMMs (2x68.7 GF) with Mt (17.2 GF) + T (68.7 GF).
// V is produced directly transposed: V^T = Wv^T @ xh^T (contraction over h,
// via the transposed weights qTh).
// ---------------------------------------------------------------------------
extern "C" void kernel_launch(void* const* d_in, const int* in_sizes, int n_in,
                              void* d_out, int out_size)
{
    (void)in_sizes; (void)n_in; (void)out_size;
    const float* x     = (const float*)d_in[0];   // (2, 4096, 2048)
    const float* qkvW  = (const float*)d_in[1];   // (2048, 6144)
    const float* oproj = (const float*)d_in[2];   // (2048, 2048)
    float* out = (float*)d_out;                   // (2, 4096, 2048)

    __half *xh, *th, *mt, *ph, *ah, *wh, *qTh, *oTh, *vTt;
    float *sc;
    cudaGetSymbolAddress((void**)&xh,  g_xh);
    cudaGetSymbolAddress((void**)&th,  g_th);
    cudaGetSymbolAddress((void**)&mt,  g_mt);
    cudaGetSymbolAddress((void**)&sc,  g_sc);
    cudaGetSymbolAddress((void**)&ph,  g_ph);
    cudaGetSymbolAddress((void**)&ah,  g_ah);
    cudaGetSymbolAddress((void**)&wh,  g_wh);
    cudaGetSymbolAddress((void**)&qTh, g_qTh);
    cudaGetSymbolAddress((void**)&oTh, g_oTh);
    cudaGetSymbolAddress((void**)&vTt, g_vTt);

    cudaFuncSetAttribute(hgemm<__half, false, false, false>,
                         cudaFuncAttributeMaxDynamicSharedMemorySize, GEMM_DYN_SMEM);
    cudaFuncSetAttribute(hgemm<float, true, false, false>,
                         cudaFuncAttributeMaxDynamicSharedMemorySize, GEMM_DYN_SMEM);
    cudaFuncSetAttribute(hgemm<__half, false, true, false>,
                         cudaFuncAttributeMaxDynamicSharedMemorySize, GEMM_DYN_SMEM);
    cudaFuncSetAttribute(hgemm<float, false, false, true>,
                         cudaFuncAttributeMaxDynamicSharedMemorySize, GEMM_DYN_SMEM);

    const int M = BB * SS;                 // 8192
    const float scale = 1.0f / sqrtf((float)DD);

    // 1) LayerNorm -> half
    ln_kernel<<<M, 256>>>(x, xh);

    // 2a) Cast qkvW -> half (same [2048, 6144] layout; rows are d-contiguous)
    {
        size_t n4 = (size_t)HH * ND / 4;
        cast_kernel<<<(unsigned)((n4 + 255) / 256), 256>>>(qkvW, wh, n4);
    }
    // 2b) Weight transposes -> half
    //     qTh rows: [0,2048)=Wq^T, [2048,4096)=Wk^T, [4096,6144)=Wv^T
    transpose_kernel<<<dim3(ND / 32, HH / 32), 256>>>(qkvW, qTh, ND, HH);
    transpose_kernel<<<dim3(HH / 32, DD / 32), 256>>>(oproj, oTh, HH, DD);

    // 3) Mt[h',h] = sum_d Wk[h',d] Wq[h,d]  (A = Wk rows, B = Wq rows, both lda/ldb=ND)
    hgemm<__half, false, false, false><<<dim3(HH / 256, HH / 128), 256, GEMM_DYN_SMEM>>>(
        wh + DD, wh, mt, nullptr, DD, ND, ND, HH, 0, 0, 0);

    // 4) V^T = Wv^T @ xh^T -> [2048, 8192] half (batch b cols at b*4096)
    hgemm<__half, false, false, false><<<dim3(M / 256, DD / 128), 256, GEMM_DYN_SMEM>>>(
        qTh + (size_t)2 * DD * HH, xh, vTt, nullptr, HH, HH, HH, M, 0, 0, 0);

    // 5) T = xh @ Mt^T -> [8192, 2048] half   (T[s,h'] = sum_h xh[s,h] Mt[h',h])
    hgemm<__half, false, false, false><<<dim3(HH / 256, M / 128), 256, GEMM_DYN_SMEM>>>(
        xh, mt, th, nullptr, HH, HH, HH, HH, 0, 0, 0);

    // 6) scores = T @ xh^T (causal block-skip) -> fp32, per batch
    hgemm<float, true, false, false><<<dim3(SS / 256, SS / 128, BB), 256, GEMM_DYN_SMEM>>>(
        th, xh, sc, nullptr, HH, HH, HH, SS,
        (size_t)SS * HH, (size_t)SS * HH, (size_t)SS * SS);

    // 7) Causal softmax: fp32 -> half probs
    softmax_kernel<<<dim3(SS, BB), 256>>>(sc, ph, scale);

    // 8) Attn = P @ (V^T)^T -> half (K-causal), B row d at vTt + d*8192 + b*4096
    hgemm<__half, false, true, false><<<dim3(DD / 256, SS / 128, BB), 256, GEMM_DYN_SMEM>>>(
        ph, vTt, ah, nullptr, SS, SS, M, DD,
        (size_t)SS * SS, (size_t)SS, (size_t)SS * DD);

    // 9) Out = attn @ oTh^T + x -> fp32
    hgemm<float, false, false, true><<<dim3(HH / 256, M / 128), 256, GEMM_DYN_SMEM>>>(
        ah, oTh, out, x, DD, DD, DD, HH, 0, 0, 0);
}

// round 17
// speedup vs baseline: 1.2740x; 1.1604x over previous
#include <cuda_runtime.h>
#include <cuda_fp16.h>
#include <math.h>
#include <stdint.h>

// Problem constants
#define BB 2
#define SS 4096
#define HH 2048
#define DD 2048
#define ND 6144   // 3*D

// ---------------------------------------------------------------------------
// Scratch (allocation-free: __device__ globals)
// ---------------------------------------------------------------------------
__device__ __half g_xh  [(size_t)BB * SS * HH];    //  32 MB  LN output
__device__ __half g_th  [(size_t)BB * SS * DD];    //  32 MB  T = x @ (Wq Wk^T)
__device__ __half g_mt  [(size_t)HH * HH];         //   8 MB  Mt[h',h] = sum_d Wk[h',d] Wq[h,d]
__device__ float  g_sc  [(size_t)BB * SS * SS];    // 128 MB  scores (fp32)
__device__ __half g_ph  [(size_t)BB * SS * SS];    //  64 MB  probs (half)
__device__ __half g_wh  [(size_t)HH * ND];         //  24 MB  qkvW cast to half (same layout)
__device__ __half g_oTh [(size_t)HH * DD];         //   8 MB  o_proj^T  (oTh[h,d] = Wo[d,h])
__device__ __half g_wvoT[(size_t)HH * HH];         //   8 MB  WvoT[h,h'] = sum_d Wo[d,h] Wv[h',d]
__device__ __half g_vwT [(size_t)HH * (BB * SS)];  //  32 MB  vwT[h,t] = (x Wv Wo)^T

// ---------------------------------------------------------------------------
// Helpers
// ---------------------------------------------------------------------------
__device__ __forceinline__ uint32_t smem_u32(const void* p) {
    uint32_t a;
    asm("{ .reg .u64 t; cvta.to.shared.u64 t, %1; cvt.u32.u64 %0, t; }" : "=r"(a) : "l"(p));
    return a;
}

__device__ __forceinline__ void cp_async16(uint32_t smem, const void* glob) {
    asm volatile("cp.async.cg.shared.global [%0], [%1], 16;" :: "r"(smem), "l"(glob));
}

__device__ __forceinline__ void ldmatrix_x4(uint32_t* r, uint32_t addr) {
    asm volatile("ldmatrix.sync.aligned.m8n8.x4.shared.b16 {%0,%1,%2,%3}, [%4];"
                 : "=r"(r[0]), "=r"(r[1]), "=r"(r[2]), "=r"(r[3]) : "r"(addr));
}

__device__ __forceinline__ void mma_f16(float* c, const uint32_t* a, const uint32_t* b) {
    asm volatile(
        "mma.sync.aligned.m16n8k16.row.col.f32.f16.f16.f32 "
        "{%0,%1,%2,%3}, {%4,%5,%6,%7}, {%8,%9}, {%0,%1,%2,%3};"
        : "+f"(c[0]), "+f"(c[1]), "+f"(c[2]), "+f"(c[3])
        : "r"(a[0]), "r"(a[1]), "r"(a[2]), "r"(a[3]), "r"(b[0]), "r"(b[1]));
}

// ---------------------------------------------------------------------------
// fp32 -> fp16 cast (same layout), vectorized
// ---------------------------------------------------------------------------
__global__ void __launch_bounds__(256) cast_kernel(const float* __restrict__ in,
                                                   __half* __restrict__ out, size_t n4)
{
    size_t i = (size_t)blockIdx.x * 256 + threadIdx.x;
    if (i < n4) {
        float4 v = ((const float4*)in)[i];
        __half2* o = (__half2*)out + i * 2;
        o[0] = __floats2half2_rn(v.x, v.y);
        o[1] = __floats2half2_rn(v.z, v.w);
    }
}

// ---------------------------------------------------------------------------
// LayerNorm: fp32 in -> half out
// ---------------------------------------------------------------------------
__global__ void __launch_bounds__(256) ln_kernel(const float* __restrict__ x,
                                                 __half* __restrict__ xh)
{
    int row = blockIdx.x;
    const float4* xr = (const float4*)(x + (size_t)row * HH);
    __half2* yh = (__half2*)(xh + (size_t)row * HH);
    int tid = threadIdx.x;

    float4 v0 = xr[tid];
    float4 v1 = xr[tid + 256];
    float s  = v0.x + v0.y + v0.z + v0.w + v1.x + v1.y + v1.z + v1.w;
    float sq = v0.x*v0.x + v0.y*v0.y + v0.z*v0.z + v0.w*v0.w
             + v1.x*v1.x + v1.y*v1.y + v1.z*v1.z + v1.w*v1.w;

    __shared__ float rs[8], rq[8];
    #pragma unroll
    for (int o = 16; o > 0; o >>= 1) {
        s  += __shfl_xor_sync(0xffffffffu, s,  o);
        sq += __shfl_xor_sync(0xffffffffu, sq, o);
    }
    if ((tid & 31) == 0) { rs[tid >> 5] = s; rq[tid >> 5] = sq; }
    __syncthreads();
    float ts = 0.f, tq = 0.f;
    #pragma unroll
    for (int i = 0; i < 8; i++) { ts += rs[i]; tq += rq[i]; }

    float mean = ts * (1.0f / HH);
    float var  = tq * (1.0f / HH) - mean * mean;
    float rstd = rsqrtf(var + 1e-6f);

    yh[tid * 2 + 0]   = __floats2half2_rn((v0.x - mean) * rstd, (v0.y - mean) * rstd);
    yh[tid * 2 + 1]   = __floats2half2_rn((v0.z - mean) * rstd, (v0.w - mean) * rstd);
    yh[512 + tid * 2] = __floats2half2_rn((v1.x - mean) * rstd, (v1.y - mean) * rstd);
    yh[513 + tid * 2] = __floats2half2_rn((v1.z - mean) * rstd, (v1.w - mean) * rstd);
}

// ---------------------------------------------------------------------------
// Tiled transpose (fp32 in -> half out): out[c*ldo + r] = in[r*ldi + c]
// ---------------------------------------------------------------------------
__global__ void __launch_bounds__(256) transpose_kernel(
    const float* __restrict__ in, __half* __restrict__ out,
    int ldi, int ldo)
{
    __shared__ float t[32][33];
    int tx = threadIdx.x & 31, ty = threadIdx.x >> 5;   // 32 x 8
    int c = blockIdx.x * 32 + tx;
    int r = blockIdx.y * 32 + ty;
    #pragma unroll
    for (int j = 0; j < 4; j++)
        t[ty + 8 * j][tx] = in[(size_t)(r + 8 * j) * ldi + c];
    __syncthreads();
    int co = blockIdx.y * 32 + tx;
    int ro = blockIdx.x * 32 + ty;
    #pragma unroll
    for (int j = 0; j < 4; j++)
        out[(size_t)(ro + 8 * j) * ldo + co] = __float2half_rn(t[tx][ty + 8 * j]);
}

// ---------------------------------------------------------------------------
// fp16 mma.sync NT GEMM: C[M,N] = A[M,K] @ B[N,K]^T (half, K-major).
// BM=128, BN=256, BK=64, 4-stage cp.async ring (prefetch distance 3),
// 8 warps of 64x64 warp tiles, 256 threads, one barrier per stage.
//   CAUSAL : skip output blocks entirely above the diagonal (scores)
//   KCAUS  : limit K loop to the diagonal (PV: A is lower-triangular)
//   RES    : C += Resid (fp32, same ldc/batch stride as C)
// ---------------------------------------------------------------------------
#define BK 64
#define STAGE_BYTES 49152            // A 16KB + B 32KB
#define NSTAGE 4
#define GEMM_DYN_SMEM (NSTAGE * STAGE_BYTES)   // 196608

template<typename CT, bool CAUSAL, bool KCAUS, bool RES>
__global__ void __launch_bounds__(256, 1) hgemm(
    const __half* __restrict__ A, const __half* __restrict__ B,
    CT* __restrict__ C, const float* __restrict__ Resid,
    int K, int lda, int ldb, int ldc,
    size_t sAz, size_t sBz, size_t sCz)
{
    const int bx = blockIdx.x, by = blockIdx.y, bz = blockIdx.z;
    if (CAUSAL && bx * 256 > by * 128 + 127) return;

    extern __shared__ char sm[];
    const uint32_t s0 = smem_u32(sm);

    const int tid = threadIdx.x;
    const int wid = tid >> 5, lane = tid & 31;
    const int wm = (wid & 1) * 64;       // 2 warps along M
    const int wn = (wid >> 1) * 64;      // 4 warps along N

    const __half* Ab = A + (size_t)bz * sAz + (size_t)(by * 128) * lda;
    const __half* Bb = B + (size_t)bz * sBz + (size_t)(bx * 256) * ldb;

    // cp.async mapping: row = tid/2, chunks (tid&1)*4 .. +3 (pairs cover 8 chunks)
    const int ldRow = tid >> 1;
    const int ldCh0 = (tid & 1) * 4;

    float acc[4][8][4];
    #pragma unroll
    for (int i = 0; i < 4; i++)
        #pragma unroll
        for (int j = 0; j < 8; j++)
            #pragma unroll
            for (int h = 0; h < 4; h++) acc[i][j][h] = 0.f;

    int nk = K / BK;
    if (KCAUS) {
        int kmax = (by + 1) * 128;       // rows in this block see cols [0, kmax)
        if (kmax < K) nk = kmax / BK;
    }

    auto load_stage = [&](int kt, int st) {
        const int k0 = kt * BK;
        const uint32_t as = s0 + st * STAGE_BYTES;
        const uint32_t bs = as + 16384;
        const uint32_t rsw = (uint32_t)(ldRow & 7);
        #pragma unroll
        for (int i = 0; i < 4; i++) {
            const int ch = ldCh0 + i;
            const uint32_t off = (uint32_t)ldRow * 128 + (((uint32_t)ch ^ rsw) << 4);
            cp_async16(as + off, Ab + (size_t)ldRow * lda + k0 + ch * 8);
        }
        #pragma unroll
        for (int j = 0; j < 2; j++) {
            const int row = ldRow + j * 128;
            #pragma unroll
            for (int i = 0; i < 4; i++) {
                const int ch = ldCh0 + i;
                const uint32_t off = (uint32_t)row * 128 + (((uint32_t)ch ^ rsw) << 4);
                cp_async16(bs + off, Bb + (size_t)row * ldb + k0 + ch * 8);
            }
        }
        asm volatile("cp.async.commit_group;" ::: "memory");
    };

    // prologue: up to 3 stages in flight
    load_stage(0, 0);
    if (nk > 1) load_stage(1, 1);
    if (nk > 2) load_stage(2, 2);

    const uint32_t rlow = (uint32_t)(lane & 7);
    const uint32_t r16  = (uint32_t)(lane & 15);

    int st = 0;
    for (int kt = 0; kt < nk; kt++) {
        if (kt + 3 <= nk) {
            asm volatile("cp.async.wait_group 2;" ::: "memory");
        } else if (kt + 2 <= nk) {
            asm volatile("cp.async.wait_group 1;" ::: "memory");
        } else {
            asm volatile("cp.async.wait_group 0;" ::: "memory");
        }
        __syncthreads();

        if (kt + 3 < nk) {
            int st2 = st + 3; if (st2 >= NSTAGE) st2 -= NSTAGE;
            load_stage(kt + 3, st2);
        }

        const uint32_t as = s0 + st * STAGE_BYTES;
        const uint32_t bs = as + 16384;

        #pragma unroll
        for (int ks = 0; ks < 4; ks++) {
            const uint32_t ch = (uint32_t)(ks * 2 + (lane >> 4));
            const uint32_t sw = ((ch ^ rlow) << 4);
            uint32_t a[4][4], b[8][2];
            #pragma unroll
            for (int mt = 0; mt < 4; mt++) {
                const uint32_t addr = as + (wm + mt * 16 + r16) * 128 + sw;
                ldmatrix_x4(a[mt], addr);
            }
            #pragma unroll
            for (int nb = 0; nb < 4; nb++) {
                uint32_t r[4];
                const uint32_t addr = bs + (wn + nb * 16 + r16) * 128 + sw;
                ldmatrix_x4(r, addr);
                b[2 * nb + 0][0] = r[0]; b[2 * nb + 0][1] = r[2];
                b[2 * nb + 1][0] = r[1]; b[2 * nb + 1][1] = r[3];
            }
            #pragma unroll
            for (int mt = 0; mt < 4; mt++)
                #pragma unroll
                for (int nt = 0; nt < 8; nt++)
                    mma_f16(acc[mt][nt], a[mt], b[nt]);
        }
        if (++st == NSTAGE) st = 0;
    }

    // epilogue
    const int qid = lane >> 2, tq = lane & 3;
    C += (size_t)bz * sCz;
    const int crow0 = by * 128 + wm;
    const int ccol0 = bx * 256 + wn;
    #pragma unroll
    for (int mt = 0; mt < 4; mt++) {
        #pragma unroll
        for (int h = 0; h < 2; h++) {
            const int row = crow0 + mt * 16 + qid + h * 8;
            CT* cr = C + (size_t)row * ldc;
            const float* rr = RES ? (Resid + (size_t)bz * sCz + (size_t)row * ldc) : nullptr;
            #pragma unroll
            for (int nt = 0; nt < 8; nt++) {
                const int col = ccol0 + nt * 8 + tq * 2;
                float vx = acc[mt][nt][2 * h + 0];
                float vy = acc[mt][nt][2 * h + 1];
                if (RES) {
                    const float2 rv = *(const float2*)(rr + col);
                    vx += rv.x; vy += rv.y;
                }
                if (sizeof(CT) == 2) {
                    *(__half2*)((__half*)cr + col) = __floats2half2_rn(vx, vy);
                } else {
                    *(float2*)((float*)cr + col) = make_float2(vx, vy);
                }
            }
        }
    }
}

// ---------------------------------------------------------------------------
// Causal softmax: fp32 scores in -> half probs out (zeros above diagonal)
// ---------------------------------------------------------------------------
__global__ void __launch_bounds__(256) softmax_kernel(
    const float* __restrict__ scores, __half* __restrict__ probs, float scale)
{
    const int r = blockIdx.x;
    const int b = blockIdx.y;
    const float* rin = scores + ((size_t)b * SS + r) * SS;
    __half* rout = probs + ((size_t)b * SS + r) * SS;
    const int len = r + 1;
    const int tid = threadIdx.x;

    __shared__ float buf[SS];
    __shared__ float red[8];

    float lmax = -1e30f;
    for (int t = tid; t < len; t += 256) {
        float v = rin[t] * scale;
        buf[t] = v;
        lmax = fmaxf(lmax, v);
    }
    #pragma unroll
    for (int o = 16; o > 0; o >>= 1)
        lmax = fmaxf(lmax, __shfl_xor_sync(0xffffffffu, lmax, o));
    if ((tid & 31) == 0) red[tid >> 5] = lmax;
    __syncthreads();
    float m = -1e30f;
    #pragma unroll
    for (int i = 0; i < 8; i++) m = fmaxf(m, red[i]);
    __syncthreads();

    float lsum = 0.f;
    for (int t = tid; t < len; t += 256) {
        float e = expf(buf[t] - m);
        buf[t] = e;
        lsum += e;
    }
    #pragma unroll
    for (int o = 16; o > 0; o >>= 1)
        lsum += __shfl_xor_sync(0xffffffffu, lsum, o);
    if ((tid & 31) == 0) red[tid >> 5] = lsum;
    __syncthreads();
    float tot = 0.f;
    #pragma unroll
    for (int i = 0; i < 8; i++) tot += red[i];
    const float inv = 1.0f / tot;

    for (int t = tid; t < len; t += 256) rout[t] = __float2half_rn(buf[t] * inv);
    const __half hz = __float2half_rn(0.f);
    for (int t = len + tid; t < SS; t += 256) rout[t] = hz;
}

// ---------------------------------------------------------------------------
// Launch
//
// Score path:  scores = x (Wq Wk^T) x^T.  Mt[h',h] = sum_d Wk[h',d] Wq[h,d]
// (d-contiguous operands = original qkvW layout cast to half), T = xh @ Mt^T,
// scores = T @ xh^T (causal).
// Value path:  out = P (x Wv Wo) + x.  WvoT[h,h'] = sum_d Wo[d,h] Wv[h',d]
// (A = o_proj^T rows, B = Wv rows of wh), vwT[h,t] = sum_{h'} WvoT[h,h'] x[t,h'],
// out = P @ vwT^T + x in ONE K-causal GEMM with fused residual.
// Deleted vs R15: O-proj GEMM (68.7 GF), qTh transpose, attn intermediate.
// ---------------------------------------------------------------------------
extern "C" void kernel_launch(void* const* d_in, const int* in_sizes, int n_in,
                              void* d_out, int out_size)
{
    (void)in_sizes; (void)n_in; (void)out_size;
    const float* x     = (const float*)d_in[0];   // (2, 4096, 2048)
    const float* qkvW  = (const float*)d_in[1];   // (2048, 6144)
    const float* oproj = (const float*)d_in[2];   // (2048, 2048)
    float* out = (float*)d_out;                   // (2, 4096, 2048)

    __half *xh, *th, *mt, *ph, *wh, *oTh, *wvoT, *vwT;
    float *sc;
    cudaGetSymbolAddress((void**)&xh,   g_xh);
    cudaGetSymbolAddress((void**)&th,   g_th);
    cudaGetSymbolAddress((void**)&mt,   g_mt);
    cudaGetSymbolAddress((void**)&sc,   g_sc);
    cudaGetSymbolAddress((void**)&ph,   g_ph);
    cudaGetSymbolAddress((void**)&wh,   g_wh);
    cudaGetSymbolAddress((void**)&oTh,  g_oTh);
    cudaGetSymbolAddress((void**)&wvoT, g_wvoT);
    cudaGetSymbolAddress((void**)&vwT,  g_vwT);

    cudaFuncSetAttribute(hgemm<__half, false, false, false>,
                         cudaFuncAttributeMaxDynamicSharedMemorySize, GEMM_DYN_SMEM);
    cudaFuncSetAttribute(hgemm<float, true, false, false>,
                         cudaFuncAttributeMaxDynamicSharedMemorySize, GEMM_DYN_SMEM);
    cudaFuncSetAttribute(hgemm<float, false, true, true>,
                         cudaFuncAttributeMaxDynamicSharedMemorySize, GEMM_DYN_SMEM);

    const int M = BB * SS;                 // 8192
    const float scale = 1.0f / sqrtf((float)DD);

    // 1) LayerNorm -> half
    ln_kernel<<<M, 256>>>(x, xh);

    // 2a) Cast qkvW -> half (same [2048, 6144] layout; rows are d-contiguous)
    {
        size_t n4 = (size_t)HH * ND / 4;
        cast_kernel<<<(unsigned)((n4 + 255) / 256), 256>>>(qkvW, wh, n4);
    }
    // 2b) o_proj^T -> half  (oTh[h,d] = Wo[d,h], d-contiguous rows)
    transpose_kernel<<<dim3(HH / 32, DD / 32), 256>>>(oproj, oTh, HH, DD);

    // 3) Mt[h',h] = sum_d Wk[h',d] Wq[h,d]
    hgemm<__half, false, false, false><<<dim3(HH / 256, HH / 128), 256, GEMM_DYN_SMEM>>>(
        wh + DD, wh, mt, nullptr, DD, ND, ND, HH, 0, 0, 0);

    // 4) WvoT[h,h'] = sum_d oTh[h,d] Wv[h',d]   (A=oTh lda=DD, B=Wv rows ldb=ND)
    hgemm<__half, false, false, false><<<dim3(HH / 256, HH / 128), 256, GEMM_DYN_SMEM>>>(
        oTh, wh + 2 * DD, wvoT, nullptr, DD, DD, ND, HH, 0, 0, 0);

    // 5) T = xh @ Mt^T -> [8192, 2048] half
    hgemm<__half, false, false, false><<<dim3(HH / 256, M / 128), 256, GEMM_DYN_SMEM>>>(
        xh, mt, th, nullptr, HH, HH, HH, HH, 0, 0, 0);

    // 6) vwT[h,t] = sum_{h'} WvoT[h,h'] xh[t,h'] -> [2048, 8192] half
    hgemm<__half, false, false, false><<<dim3(M / 256, HH / 128), 256, GEMM_DYN_SMEM>>>(
        wvoT, xh, vwT, nullptr, HH, HH, HH, M, 0, 0, 0);

    // 7) scores = T @ xh^T (causal block-skip) -> fp32, per batch
    hgemm<float, true, false, false><<<dim3(SS / 256, SS / 128, BB), 256, GEMM_DYN_SMEM>>>(
        th, xh, sc, nullptr, HH, HH, HH, SS,
        (size_t)SS * HH, (size_t)SS * HH, (size_t)SS * SS);

    // 8) Causal softmax: fp32 -> half probs
    softmax_kernel<<<dim3(SS, BB), 256>>>(sc, ph, scale);

    // 9) out = P @ vwT^T + x -> fp32 (K-causal + fused residual)
    //    B row h at vwT + h*M, batch offset b*4096 columns (sBz = SS)
    hgemm<float, false, true, true><<<dim3(HH / 256, SS / 128, BB), 256, GEMM_DYN_SMEM>>>(
        ph, vwT, out, x, SS, SS, M, HH,
        (size_t)SS * SS, (size_t)SS, (size_t)SS * HH);
}